// round 4
// baseline (speedup 1.0000x reference)
#include <cuda_runtime.h>
#include <cuda_bf16.h>
#include <cstdint>
#include <cstddef>

#define TSEQ  512
#define HID   128
#define GATES 512
#define INP   256
#define BATCH 256

typedef unsigned long long ull;

// Scratch (device globals: no runtime allocation allowed)
__device__ float g_gx[(size_t)BATCH * TSEQ * GATES];  // x@W_ih^T + (b_ih+b_hh)
__device__ float g_hfin[BATCH * HID];                 // final hidden state

// ---------- packed f32x2 helpers (2x fp32 FMA rate on sm_103a) ----------
__device__ __forceinline__ ull ffma2(ull a, ull b, ull c) {
    ull d; asm("fma.rn.f32x2 %0, %1, %2, %3;" : "=l"(d) : "l"(a), "l"(b), "l"(c));
    return d;
}
__device__ __forceinline__ ull dup2(float a) {
    ull r; asm("mov.b64 %0, {%1, %1};" : "=l"(r) : "f"(a)); return r;
}
__device__ __forceinline__ ull pack2(float x, float y) {
    ull r; asm("mov.b64 %0, {%1, %2};" : "=l"(r) : "f"(x), "f"(y)); return r;
}
__device__ __forceinline__ float2 unpack2(ull v) {
    float2 r; asm("mov.b64 {%0, %1}, %2;" : "=f"(r.x), "=f"(r.y) : "l"(v)); return r;
}
__device__ __forceinline__ float sig_f(float x) {
    return __fdividef(1.0f, 1.0f + __expf(-x));
}
__device__ __forceinline__ float tanh_f(float x) {
    return __fdividef(2.0f, 1.0f + __expf(-2.0f * x)) - 1.0f;
}

// =====================================================================
// Kernel 1: gx[m,n] = sum_k x[m,k]*W_ih[n,k] + (b_ih[n]+b_hh[n])
// M=131072, N=512, K=256. BM=BN=128, BK=16, 256 threads, 8x8 microtile.
// =====================================================================
#define BM 128
#define BN 128
#define BK 16
#define LDT 132

__global__ __launch_bounds__(256, 2)
void gemm_gx(const float* __restrict__ x, const float* __restrict__ Wih,
             const float* __restrict__ bih, const float* __restrict__ bhh) {
    __shared__ float As[BK][LDT];
    __shared__ float Bs[BK][LDT];

    const int tid = threadIdx.x;
    const int m0 = blockIdx.x * BM;
    const int n0 = blockIdx.y * BN;
    const int tm = (tid >> 4) << 3;   // 0..120
    const int tn = (tid & 15) << 3;   // 0..120

    ull acc[8][4];
#pragma unroll
    for (int i = 0; i < 8; i++)
#pragma unroll
        for (int j = 0; j < 4; j++) acc[i][j] = 0ull;

    for (int kk = 0; kk < INP / BK; kk++) {
        const int k0 = kk * BK;
        __syncthreads();
#pragma unroll
        for (int i = 0; i < 2; i++) {
            int li = tid + i * 256;
            int row = li >> 2, kq = li & 3;
            float4 va = *(const float4*)(x + (size_t)(m0 + row) * INP + k0 + kq * 4);
            As[kq * 4 + 0][row] = va.x; As[kq * 4 + 1][row] = va.y;
            As[kq * 4 + 2][row] = va.z; As[kq * 4 + 3][row] = va.w;
            float4 vb = *(const float4*)(Wih + (size_t)(n0 + row) * INP + k0 + kq * 4);
            Bs[kq * 4 + 0][row] = vb.x; Bs[kq * 4 + 1][row] = vb.y;
            Bs[kq * 4 + 2][row] = vb.z; Bs[kq * 4 + 3][row] = vb.w;
        }
        __syncthreads();
#pragma unroll
        for (int k = 0; k < BK; k++) {
            float4 a0 = *(const float4*)&As[k][tm];
            float4 a1 = *(const float4*)&As[k][tm + 4];
            const ulonglong2* bp = (const ulonglong2*)&Bs[k][tn];
            ulonglong2 bq0 = bp[0], bq1 = bp[1];
            float av[8] = {a0.x, a0.y, a0.z, a0.w, a1.x, a1.y, a1.z, a1.w};
#pragma unroll
            for (int i = 0; i < 8; i++) {
                ull aw = dup2(av[i]);
                acc[i][0] = ffma2(aw, bq0.x, acc[i][0]);
                acc[i][1] = ffma2(aw, bq0.y, acc[i][1]);
                acc[i][2] = ffma2(aw, bq1.x, acc[i][2]);
                acc[i][3] = ffma2(aw, bq1.y, acc[i][3]);
            }
        }
    }

    float bsv[8];
#pragma unroll
    for (int j = 0; j < 8; j++) bsv[j] = bih[n0 + tn + j] + bhh[n0 + tn + j];
#pragma unroll
    for (int i = 0; i < 8; i++) {
        float* gp = g_gx + (size_t)(m0 + tm + i) * GATES + n0 + tn;
        float2 p0 = unpack2(acc[i][0]), p1 = unpack2(acc[i][1]);
        float2 p2 = unpack2(acc[i][2]), p3 = unpack2(acc[i][3]);
        *(float4*)gp       = make_float4(p0.x + bsv[0], p0.y + bsv[1], p1.x + bsv[2], p1.y + bsv[3]);
        *(float4*)(gp + 4) = make_float4(p2.x + bsv[4], p2.y + bsv[5], p3.x + bsv[6], p3.y + bsv[7]);
    }
}

// =====================================================================
// Kernel 2: LSTM recurrence. 128 blocks x 512 threads; block owns batch
// rows (2b, 2b+1). Thread n owns gate output n. K packed in pairs for
// f32x2 (no runtime dup): W_hh[n][0:64] in regs (32 ull), [64:128] in smem.
// =====================================================================
#define KRQ 16   // register float4-groups per row (64 floats)
#define KSQ 16   // smem float4-groups per row (64 floats)
#define WSP_BYTES (KSQ * 512 * 16)          // 131072
#define LSTM_SMEM (WSP_BYTES + 1024 + 4096) // + h0f/h1f + ga

__global__ __launch_bounds__(512, 1)
void lstm_kernel(const float* __restrict__ Whh) {
    extern __shared__ char smem[];
    ulonglong2* wsp2 = (ulonglong2*)smem;                  // [KSQ][512]
    float* h0f = (float*)(smem + WSP_BYTES);               // 128 floats
    float* h1f = h0f + 128;
    float2* ga = (float2*)(smem + WSP_BYTES + 1024);       // [512]

    const int n = threadIdx.x;
    const int b0 = blockIdx.x * 2;
    const int b1 = b0 + 1;

    // preload weights: regs hold k=0..63 as packed pairs, smem holds k=64..127
    const float4* wrow4 = (const float4*)(Whh + (size_t)n * HID);
    ull wregp[2 * KRQ];
#pragma unroll
    for (int q = 0; q < KRQ; q++) {
        float4 v = wrow4[q];
        wregp[2 * q]     = pack2(v.x, v.y);
        wregp[2 * q + 1] = pack2(v.z, v.w);
    }
#pragma unroll
    for (int p = 0; p < KSQ; p++) {
        float4 v = wrow4[KRQ + p];
        ulonglong2 w;
        w.x = pack2(v.x, v.y);
        w.y = pack2(v.z, v.w);
        wsp2[p * 512 + n] = w;
    }

    if (n < 128) { h0f[n] = 0.0f; h1f[n] = 0.0f; }
    __syncthreads();

    const float* gx0p = g_gx + ((size_t)b0 * TSEQ) * GATES + n;
    const float* gx1p = g_gx + ((size_t)b1 * TSEQ) * GATES + n;
    float gxa = gx0p[0], gxb = gx1p[0];
    float c0 = 0.0f, c1 = 0.0f;

    for (int t = 0; t < TSEQ; t++) {
        float gna = 0.0f, gnb = 0.0f;
        if (t + 1 < TSEQ) {
            gna = gx0p[(size_t)(t + 1) * GATES];
            gnb = gx1p[(size_t)(t + 1) * GATES];
        }
        ull a0 = pack2(gxa, 0.0f);
        ull a1 = pack2(gxb, 0.0f);
        const ulonglong2* h02 = (const ulonglong2*)h0f;  // 32 entries
        const ulonglong2* h12 = (const ulonglong2*)h1f;
#pragma unroll
        for (int q = 0; q < KRQ; q++) {            // k = 4q .. 4q+3
            ulonglong2 hA = h02[q];
            ulonglong2 hB = h12[q];
            a0 = ffma2(wregp[2 * q],     hA.x, a0);
            a0 = ffma2(wregp[2 * q + 1], hA.y, a0);
            a1 = ffma2(wregp[2 * q],     hB.x, a1);
            a1 = ffma2(wregp[2 * q + 1], hB.y, a1);
        }
#pragma unroll
        for (int p = 0; p < KSQ; p++) {            // k = 64 + 4p ..
            ulonglong2 w  = wsp2[p * 512 + n];
            ulonglong2 hA = h02[KRQ + p];
            ulonglong2 hB = h12[KRQ + p];
            a0 = ffma2(w.x, hA.x, a0);
            a0 = ffma2(w.y, hA.y, a0);
            a1 = ffma2(w.x, hB.x, a1);
            a1 = ffma2(w.y, hB.y, a1);
        }
        float2 s0 = unpack2(a0), s1 = unpack2(a1);
        float pre0 = s0.x + s0.y, pre1 = s1.x + s1.y;
        float act0, act1;
        if (n >= 256 && n < 384) { act0 = tanh_f(pre0); act1 = tanh_f(pre1); }
        else                     { act0 = sig_f(pre0);  act1 = sig_f(pre1);  }
        ga[n] = make_float2(act0, act1);
        __syncthreads();   // gates written; all h reads done
        if (n < 128) {
            float2 gi = ga[n], gf = ga[n + 128], gg = ga[n + 256], go = ga[n + 384];
            c0 = gf.x * c0 + gi.x * gg.x;
            c1 = gf.y * c1 + gi.y * gg.y;
            h0f[n] = go.x * tanh_f(c0);
            h1f[n] = go.y * tanh_f(c1);
        }
        __syncthreads();   // h updated
        gxa = gna; gxb = gnb;
    }

    if (n < 128) {
        g_hfin[b0 * HID + n] = h0f[n];
        g_hfin[b1 * HID + n] = h1f[n];
    }
}

// =====================================================================
// Kernel 3: MLP head. One block per batch row, 128 threads.
// =====================================================================
__global__ __launch_bounds__(128)
void mlp_kernel(const float* __restrict__ W1, const float* __restrict__ b1,
                const float* __restrict__ W2, const float* __restrict__ b2,
                const float* __restrict__ W3, const float* __restrict__ b3,
                float* __restrict__ out) {
    __shared__ float h[128];
    __shared__ float h1[64];
    __shared__ float h2[32];
    const int b = blockIdx.x;
    const int t = threadIdx.x;

    h[t] = g_hfin[b * HID + t];
    __syncthreads();
    if (t < 64) {
        float s = b1[t];
        const float* w = W1 + t * 128;
#pragma unroll 8
        for (int k = 0; k < 128; k++) s += w[k] * h[k];
        h1[t] = fmaxf(s, 0.0f);
    }
    __syncthreads();
    if (t < 32) {
        float s = b2[t];
        const float* w = W2 + t * 64;
#pragma unroll 8
        for (int k = 0; k < 64; k++) s += w[k] * h1[k];
        h2[t] = fmaxf(s, 0.0f);
    }
    __syncthreads();
    if (t < 4) {
        float s = b3[t];
        const float* w = W3 + t * 32;
#pragma unroll
        for (int k = 0; k < 32; k++) s += w[k] * h2[k];
        out[b * 4 + t] = s;
    }
}

// =====================================================================
extern "C" void kernel_launch(void* const* d_in, const int* in_sizes, int n_in,
                              void* d_out, int out_size) {
    const float* x    = (const float*)d_in[0];
    const float* Wih  = (const float*)d_in[1];
    const float* Whh  = (const float*)d_in[2];
    const float* bih  = (const float*)d_in[3];
    const float* bhh  = (const float*)d_in[4];
    const float* W1   = (const float*)d_in[5];
    const float* b1   = (const float*)d_in[6];
    const float* W2   = (const float*)d_in[7];
    const float* b2   = (const float*)d_in[8];
    const float* W3   = (const float*)d_in[9];
    const float* b3   = (const float*)d_in[10];
    float* out = (float*)d_out;

    cudaFuncSetAttribute(lstm_kernel, cudaFuncAttributeMaxDynamicSharedMemorySize, LSTM_SMEM);

    dim3 ggrid((BATCH * TSEQ) / BM, GATES / BN);
    gemm_gx<<<ggrid, 256>>>(x, Wih, bih, bhh);
    lstm_kernel<<<BATCH / 2, 512, LSTM_SMEM>>>(Whh);
    mlp_kernel<<<BATCH, 128>>>(W1, b1, W2, b2, W3, b3, out);
}

// round 6
// speedup vs baseline: 1.0685x; 1.0685x over previous
#include <cuda_runtime.h>
#include <cuda_bf16.h>
#include <cstdint>
#include <cstddef>

#define TSEQ  512
#define HID   128
#define GATES 512
#define INP   256
#define BATCH 256

typedef unsigned long long ull;

// -------- device-global scratch (no runtime allocation allowed) --------
__device__ float g_gx[(size_t)BATCH * TSEQ * GATES];   // 256 MB
__device__ float g_hfin[BATCH * HID];

#define MTILES 8192                 // (BATCH*TSEQ)/16
#define NTILES 64                   // GATES/8
#define KSTEPS 16                   // INP/16
__device__ uint32_t g_ah[(size_t)MTILES * KSTEPS * 32 * 4];  // 64 MB
__device__ uint32_t g_al[(size_t)MTILES * KSTEPS * 32 * 4];  // 64 MB
__device__ uint32_t g_bh[(size_t)NTILES * KSTEPS * 32 * 2];  // 256 KB
__device__ uint32_t g_bl[(size_t)NTILES * KSTEPS * 32 * 2];  // 256 KB

// ---------------- helpers ----------------
__device__ __forceinline__ ull ffma2(ull a, ull b, ull c) {
    ull d; asm("fma.rn.f32x2 %0, %1, %2, %3;" : "=l"(d) : "l"(a), "l"(b), "l"(c));
    return d;
}
__device__ __forceinline__ ull pack2(float x, float y) {
    ull r; asm("mov.b64 %0, {%1, %2};" : "=l"(r) : "f"(x), "f"(y)); return r;
}
__device__ __forceinline__ float2 unpack2(ull v) {
    float2 r; asm("mov.b64 {%0, %1}, %2;" : "=f"(r.x), "=f"(r.y) : "l"(v)); return r;
}
__device__ __forceinline__ float sig_f(float x) {
    return __fdividef(1.0f, 1.0f + __expf(-x));
}
__device__ __forceinline__ float tanh_f(float x) {
    return __fdividef(2.0f, 1.0f + __expf(-2.0f * x)) - 1.0f;
}
// pack two fp32 -> bf16x2 (lo element in low 16 bits)
__device__ __forceinline__ uint32_t bfpair(float lo, float hi) {
    uint32_t r; asm("cvt.rn.bf16x2.f32 %0, %1, %2;" : "=r"(r) : "f"(hi), "f"(lo));
    return r;
}
// hi/lo split of a pair: h = bf16 pair, l = residual pair
__device__ __forceinline__ void split_pair(float e0, float e1, uint32_t& h, uint32_t& l) {
    h = bfpair(e0, e1);
    float h0 = __uint_as_float(h << 16);
    float h1 = __uint_as_float(h & 0xFFFF0000u);
    l = bfpair(e0 - h0, e1 - h1);
}

__device__ __forceinline__ void mma_bf16(float* c, const uint4& a, const uint2& b) {
    asm volatile(
        "mma.sync.aligned.m16n8k16.row.col.f32.bf16.bf16.f32 "
        "{%0,%1,%2,%3}, {%4,%5,%6,%7}, {%8,%9}, {%0,%1,%2,%3};"
        : "+f"(c[0]), "+f"(c[1]), "+f"(c[2]), "+f"(c[3])
        : "r"(a.x), "r"(a.y), "r"(a.z), "r"(a.w), "r"(b.x), "r"(b.y));
}

// =====================================================================
// Kernel 0: convert x and W_ih into fragment-ordered bf16 hi/lo arrays.
// A frag (m16n8k16): r0=(m, k) r1=(m+8, k) r2=(m, k+8) r3=(m+8, k+8),
//   m = lane/4, k-pair = (lane%4)*2. B frag: r0=(n=lane/4, k), r1=(n, k+8).
// =====================================================================
__global__ __launch_bounds__(256)
void prep_frags(const float* __restrict__ x, const float* __restrict__ Wih) {
    int gw = (blockIdx.x * 256 + threadIdx.x) >> 5;
    int lane = threadIdx.x & 31;
    if (gw < MTILES * KSTEPS) {
        int tile = gw >> 4, ks = gw & 15;
        int m = tile * 16 + (lane >> 2);
        int k = ks * 16 + (lane & 3) * 2;
        const float* base = x + (size_t)m * INP + k;
        float2 p0 = *(const float2*)(base);
        float2 p1 = *(const float2*)(base + 8 * INP);
        float2 p2 = *(const float2*)(base + 8);
        float2 p3 = *(const float2*)(base + 8 * INP + 8);
        uint4 h, l;
        split_pair(p0.x, p0.y, h.x, l.x);
        split_pair(p1.x, p1.y, h.y, l.y);
        split_pair(p2.x, p2.y, h.z, l.z);
        split_pair(p3.x, p3.y, h.w, l.w);
        size_t o = ((size_t)gw * 32 + lane) * 4;
        *(uint4*)(g_ah + o) = h;
        *(uint4*)(g_al + o) = l;
    } else if (gw < MTILES * KSTEPS + NTILES * KSTEPS) {
        int w = gw - MTILES * KSTEPS;
        int tile = w >> 4, ks = w & 15;
        int n = tile * 8 + (lane >> 2);
        int k = ks * 16 + (lane & 3) * 2;
        const float* base = Wih + (size_t)n * INP + k;
        float2 p0 = *(const float2*)(base);
        float2 p1 = *(const float2*)(base + 8);
        uint2 h, l;
        split_pair(p0.x, p0.y, h.x, l.x);
        split_pair(p1.x, p1.y, h.y, l.y);
        size_t o = ((size_t)w * 32 + lane) * 2;
        *(uint2*)(g_bh + o) = h;
        *(uint2*)(g_bl + o) = l;
    }
}

// =====================================================================
// Kernel 1: gx = x@W_ih^T + bias via mma.sync bf16 hi/lo (3 passes).
// CTA 128x128, 8 warps, warp tile 64x32 (4 m16-tiles x 4 n8-tiles).
// No smem: fragments LDG'd directly from pre-fragmented arrays.
// =====================================================================
__global__ __launch_bounds__(256)
void gemm_mma(const float* __restrict__ bih, const float* __restrict__ bhh) {
    const int wid = threadIdx.x >> 5;
    const int lane = threadIdx.x & 31;
    const int mt0 = blockIdx.y * 8 + (wid >> 2) * 4;   // m16-tile base
    const int nt0 = blockIdx.x * 16 + (wid & 3) * 4;   // n8-tile base

    float acc[4][4][4];
#pragma unroll
    for (int mi = 0; mi < 4; mi++)
#pragma unroll
        for (int ni = 0; ni < 4; ni++)
#pragma unroll
            for (int q = 0; q < 4; q++) acc[mi][ni][q] = 0.0f;

    uint4 ah[2][4], al[2][4];
    uint2 bh[2][4], bl[2][4];

#pragma unroll
    for (int mi = 0; mi < 4; mi++) {
        size_t o = (((size_t)(mt0 + mi) * KSTEPS + 0) * 32 + lane) * 4;
        ah[0][mi] = *(const uint4*)(g_ah + o);
        al[0][mi] = *(const uint4*)(g_al + o);
    }
#pragma unroll
    for (int ni = 0; ni < 4; ni++) {
        size_t o = (((size_t)(nt0 + ni) * KSTEPS + 0) * 32 + lane) * 2;
        bh[0][ni] = *(const uint2*)(g_bh + o);
        bl[0][ni] = *(const uint2*)(g_bl + o);
    }

#pragma unroll
    for (int ks = 0; ks < KSTEPS; ks++) {
        const int cur = ks & 1, nxt = cur ^ 1;
        if (ks + 1 < KSTEPS) {
#pragma unroll
            for (int mi = 0; mi < 4; mi++) {
                size_t o = (((size_t)(mt0 + mi) * KSTEPS + ks + 1) * 32 + lane) * 4;
                ah[nxt][mi] = *(const uint4*)(g_ah + o);
                al[nxt][mi] = *(const uint4*)(g_al + o);
            }
#pragma unroll
            for (int ni = 0; ni < 4; ni++) {
                size_t o = (((size_t)(nt0 + ni) * KSTEPS + ks + 1) * 32 + lane) * 2;
                bh[nxt][ni] = *(const uint2*)(g_bh + o);
                bl[nxt][ni] = *(const uint2*)(g_bl + o);
            }
        }
#pragma unroll
        for (int mi = 0; mi < 4; mi++)
#pragma unroll
            for (int ni = 0; ni < 4; ni++) {
                mma_bf16(acc[mi][ni], ah[cur][mi], bh[cur][ni]);
                mma_bf16(acc[mi][ni], al[cur][mi], bh[cur][ni]);
                mma_bf16(acc[mi][ni], ah[cur][mi], bl[cur][ni]);
            }
    }

    // epilogue: bias + store
#pragma unroll
    for (int ni = 0; ni < 4; ni++) {
        const int c = (nt0 + ni) * 8 + (lane & 3) * 2;
        const float bv0 = bih[c] + bhh[c];
        const float bv1 = bih[c + 1] + bhh[c + 1];
#pragma unroll
        for (int mi = 0; mi < 4; mi++) {
            const int m = (mt0 + mi) * 16 + (lane >> 2);
            float2 v0 = make_float2(acc[mi][ni][0] + bv0, acc[mi][ni][1] + bv1);
            float2 v1 = make_float2(acc[mi][ni][2] + bv0, acc[mi][ni][3] + bv1);
            *(float2*)(g_gx + (size_t)m * GATES + c) = v0;
            *(float2*)(g_gx + (size_t)(m + 8) * GATES + c) = v1;
        }
    }
}

// =====================================================================
// Kernel 2: LSTM recurrence (unchanged from passing round-3 kernel)
// =====================================================================
#define KRQ 16
#define KSQ 16
#define WSP_BYTES (KSQ * 512 * 16)
#define LSTM_SMEM (WSP_BYTES + 1024 + 4096)

__global__ __launch_bounds__(512, 1)
void lstm_kernel(const float* __restrict__ Whh) {
    extern __shared__ char smem[];
    ulonglong2* wsp2 = (ulonglong2*)smem;
    float* h0f = (float*)(smem + WSP_BYTES);
    float* h1f = h0f + 128;
    float2* ga = (float2*)(smem + WSP_BYTES + 1024);

    const int n = threadIdx.x;
    const int b0 = blockIdx.x * 2;
    const int b1 = b0 + 1;

    const float4* wrow4 = (const float4*)(Whh + (size_t)n * HID);
    ull wregp[2 * KRQ];
#pragma unroll
    for (int q = 0; q < KRQ; q++) {
        float4 v = wrow4[q];
        wregp[2 * q]     = pack2(v.x, v.y);
        wregp[2 * q + 1] = pack2(v.z, v.w);
    }
#pragma unroll
    for (int p = 0; p < KSQ; p++) {
        float4 v = wrow4[KRQ + p];
        ulonglong2 w;
        w.x = pack2(v.x, v.y);
        w.y = pack2(v.z, v.w);
        wsp2[p * 512 + n] = w;
    }

    if (n < 128) { h0f[n] = 0.0f; h1f[n] = 0.0f; }
    __syncthreads();

    const float* gx0p = g_gx + ((size_t)b0 * TSEQ) * GATES + n;
    const float* gx1p = g_gx + ((size_t)b1 * TSEQ) * GATES + n;
    float gxa = gx0p[0], gxb = gx1p[0];
    float c0 = 0.0f, c1 = 0.0f;

    for (int t = 0; t < TSEQ; t++) {
        float gna = 0.0f, gnb = 0.0f;
        if (t + 1 < TSEQ) {
            gna = gx0p[(size_t)(t + 1) * GATES];
            gnb = gx1p[(size_t)(t + 1) * GATES];
        }
        ull a0 = pack2(gxa, 0.0f);
        ull a1 = pack2(gxb, 0.0f);
        const ulonglong2* h02 = (const ulonglong2*)h0f;
        const ulonglong2* h12 = (const ulonglong2*)h1f;
#pragma unroll
        for (int q = 0; q < KRQ; q++) {
            ulonglong2 hA = h02[q];
            ulonglong2 hB = h12[q];
            a0 = ffma2(wregp[2 * q],     hA.x, a0);
            a0 = ffma2(wregp[2 * q + 1], hA.y, a0);
            a1 = ffma2(wregp[2 * q],     hB.x, a1);
            a1 = ffma2(wregp[2 * q + 1], hB.y, a1);
        }
#pragma unroll
        for (int p = 0; p < KSQ; p++) {
            ulonglong2 w  = wsp2[p * 512 + n];
            ulonglong2 hA = h02[KRQ + p];
            ulonglong2 hB = h12[KRQ + p];
            a0 = ffma2(w.x, hA.x, a0);
            a0 = ffma2(w.y, hA.y, a0);
            a1 = ffma2(w.x, hB.x, a1);
            a1 = ffma2(w.y, hB.y, a1);
        }
        float2 s0 = unpack2(a0), s1 = unpack2(a1);
        float pre0 = s0.x + s0.y, pre1 = s1.x + s1.y;
        float act0, act1;
        if (n >= 256 && n < 384) { act0 = tanh_f(pre0); act1 = tanh_f(pre1); }
        else                     { act0 = sig_f(pre0);  act1 = sig_f(pre1);  }
        ga[n] = make_float2(act0, act1);
        __syncthreads();
        if (n < 128) {
            float2 gi = ga[n], gf = ga[n + 128], gg = ga[n + 256], go = ga[n + 384];
            c0 = gf.x * c0 + gi.x * gg.x;
            c1 = gf.y * c1 + gi.y * gg.y;
            h0f[n] = go.x * tanh_f(c0);
            h1f[n] = go.y * tanh_f(c1);
        }
        __syncthreads();
        gxa = gna; gxb = gnb;
    }

    if (n < 128) {
        g_hfin[b0 * HID + n] = h0f[n];
        g_hfin[b1 * HID + n] = h1f[n];
    }
}

// =====================================================================
// Kernel 3: MLP head (unchanged)
// =====================================================================
__global__ __launch_bounds__(128)
void mlp_kernel(const float* __restrict__ W1, const float* __restrict__ b1,
                const float* __restrict__ W2, const float* __restrict__ b2,
                const float* __restrict__ W3, const float* __restrict__ b3,
                float* __restrict__ out) {
    __shared__ float h[128];
    __shared__ float h1[64];
    __shared__ float h2[32];
    const int b = blockIdx.x;
    const int t = threadIdx.x;

    h[t] = g_hfin[b * HID + t];
    __syncthreads();
    if (t < 64) {
        float s = b1[t];
        const float* w = W1 + t * 128;
#pragma unroll 8
        for (int k = 0; k < 128; k++) s += w[k] * h[k];
        h1[t] = fmaxf(s, 0.0f);
    }
    __syncthreads();
    if (t < 32) {
        float s = b2[t];
        const float* w = W2 + t * 64;
#pragma unroll 8
        for (int k = 0; k < 64; k++) s += w[k] * h1[k];
        h2[t] = fmaxf(s, 0.0f);
    }
    __syncthreads();
    if (t < 4) {
        float s = b3[t];
        const float* w = W3 + t * 32;
#pragma unroll
        for (int k = 0; k < 32; k++) s += w[k] * h2[k];
        out[b * 4 + t] = s;
    }
}

// =====================================================================
extern "C" void kernel_launch(void* const* d_in, const int* in_sizes, int n_in,
                              void* d_out, int out_size) {
    const float* x    = (const float*)d_in[0];
    const float* Wih  = (const float*)d_in[1];
    const float* Whh  = (const float*)d_in[2];
    const float* bih  = (const float*)d_in[3];
    const float* bhh  = (const float*)d_in[4];
    const float* W1   = (const float*)d_in[5];
    const float* b1   = (const float*)d_in[6];
    const float* W2   = (const float*)d_in[7];
    const float* b2   = (const float*)d_in[8];
    const float* W3   = (const float*)d_in[9];
    const float* b3   = (const float*)d_in[10];
    float* out = (float*)d_out;

    cudaFuncSetAttribute(lstm_kernel, cudaFuncAttributeMaxDynamicSharedMemorySize, LSTM_SMEM);

    // pre-pass: fragment-order bf16 hi/lo conversion
    int total_warps = MTILES * KSTEPS + NTILES * KSTEPS;
    prep_frags<<<(total_warps + 7) / 8, 256>>>(x, Wih);

    // tensor-core GEMM: grid (N-tiles, M-tiles) so N-tiles of same M adjacent
    dim3 ggrid(GATES / 128, (BATCH * TSEQ) / 128);   // (4, 1024)
    gemm_mma<<<ggrid, 256>>>(bih, bhh);

    lstm_kernel<<<BATCH / 2, 512, LSTM_SMEM>>>(Whh);
    mlp_kernel<<<BATCH, 128>>>(W1, b1, W2, b2, W3, b3, out);
}

// round 7
// speedup vs baseline: 1.1493x; 1.0756x over previous
#include <cuda_runtime.h>
#include <cuda_bf16.h>
#include <cstdint>
#include <cstddef>

#define TSEQ  512
#define HID   128
#define GATES 512
#define INP   256
#define BATCH 256

typedef unsigned long long ull;

// -------- device-global scratch (no runtime allocation allowed) --------
__device__ float g_gx[(size_t)BATCH * TSEQ * GATES];   // 256 MB
__device__ float g_hfin[BATCH * HID];

#define MTILES 8192                 // (BATCH*TSEQ)/16
#define NTILES 64                   // GATES/8
#define KSTEPS 16                   // INP/16
__device__ uint32_t g_ah[(size_t)MTILES * KSTEPS * 32 * 4];  // 64 MB
__device__ uint32_t g_al[(size_t)MTILES * KSTEPS * 32 * 4];  // 64 MB
__device__ uint32_t g_bh[(size_t)NTILES * KSTEPS * 32 * 2];  // 256 KB
__device__ uint32_t g_bl[(size_t)NTILES * KSTEPS * 32 * 2];  // 256 KB

// ---------------- helpers ----------------
__device__ __forceinline__ ull ffma2(ull a, ull b, ull c) {
    ull d; asm("fma.rn.f32x2 %0, %1, %2, %3;" : "=l"(d) : "l"(a), "l"(b), "l"(c));
    return d;
}
__device__ __forceinline__ ull pack2(float x, float y) {
    ull r; asm("mov.b64 %0, {%1, %2};" : "=l"(r) : "f"(x), "f"(y)); return r;
}
__device__ __forceinline__ float2 unpack2(ull v) {
    float2 r; asm("mov.b64 {%0, %1}, %2;" : "=f"(r.x), "=f"(r.y) : "l"(v)); return r;
}
__device__ __forceinline__ float sig_f(float x) {
    return __fdividef(1.0f, 1.0f + __expf(-x));
}
__device__ __forceinline__ float tanh_f(float x) {
    return __fdividef(2.0f, 1.0f + __expf(-2.0f * x)) - 1.0f;
}
// pack two fp32 -> bf16x2 (lo element in low 16 bits)
__device__ __forceinline__ uint32_t bfpair(float lo, float hi) {
    uint32_t r; asm("cvt.rn.bf16x2.f32 %0, %1, %2;" : "=r"(r) : "f"(hi), "f"(lo));
    return r;
}
// hi/lo split of a pair: h = bf16 pair, l = residual pair
__device__ __forceinline__ void split_pair(float e0, float e1, uint32_t& h, uint32_t& l) {
    h = bfpair(e0, e1);
    float h0 = __uint_as_float(h << 16);
    float h1 = __uint_as_float(h & 0xFFFF0000u);
    l = bfpair(e0 - h0, e1 - h1);
}

__device__ __forceinline__ void mma_bf16(float* c, const uint4& a, const uint2& b) {
    asm volatile(
        "mma.sync.aligned.m16n8k16.row.col.f32.bf16.bf16.f32 "
        "{%0,%1,%2,%3}, {%4,%5,%6,%7}, {%8,%9}, {%0,%1,%2,%3};"
        : "+f"(c[0]), "+f"(c[1]), "+f"(c[2]), "+f"(c[3])
        : "r"(a.x), "r"(a.y), "r"(a.z), "r"(a.w), "r"(b.x), "r"(b.y));
}

// =====================================================================
// Kernel 0: convert x and W_ih into fragment-ordered bf16 hi/lo arrays.
// =====================================================================
__global__ __launch_bounds__(256)
void prep_frags(const float* __restrict__ x, const float* __restrict__ Wih) {
    int gw = (blockIdx.x * 256 + threadIdx.x) >> 5;
    int lane = threadIdx.x & 31;
    if (gw < MTILES * KSTEPS) {
        int tile = gw >> 4, ks = gw & 15;
        int m = tile * 16 + (lane >> 2);
        int k = ks * 16 + (lane & 3) * 2;
        const float* base = x + (size_t)m * INP + k;
        float2 p0 = *(const float2*)(base);
        float2 p1 = *(const float2*)(base + 8 * INP);
        float2 p2 = *(const float2*)(base + 8);
        float2 p3 = *(const float2*)(base + 8 * INP + 8);
        uint4 h, l;
        split_pair(p0.x, p0.y, h.x, l.x);
        split_pair(p1.x, p1.y, h.y, l.y);
        split_pair(p2.x, p2.y, h.z, l.z);
        split_pair(p3.x, p3.y, h.w, l.w);
        size_t o = ((size_t)gw * 32 + lane) * 4;
        *(uint4*)(g_ah + o) = h;
        *(uint4*)(g_al + o) = l;
    } else if (gw < MTILES * KSTEPS + NTILES * KSTEPS) {
        int w = gw - MTILES * KSTEPS;
        int tile = w >> 4, ks = w & 15;
        int n = tile * 8 + (lane >> 2);
        int k = ks * 16 + (lane & 3) * 2;
        const float* base = Wih + (size_t)n * INP + k;
        float2 p0 = *(const float2*)(base);
        float2 p1 = *(const float2*)(base + 8);
        uint2 h, l;
        split_pair(p0.x, p0.y, h.x, l.x);
        split_pair(p1.x, p1.y, h.y, l.y);
        size_t o = ((size_t)w * 32 + lane) * 2;
        *(uint2*)(g_bh + o) = h;
        *(uint2*)(g_bl + o) = l;
    }
}

// =====================================================================
// Kernel 1: gx = x@W_ih^T + bias via mma.sync bf16 hi/lo (3 passes).
// =====================================================================
__global__ __launch_bounds__(256)
void gemm_mma(const float* __restrict__ bih, const float* __restrict__ bhh) {
    const int wid = threadIdx.x >> 5;
    const int lane = threadIdx.x & 31;
    const int mt0 = blockIdx.y * 8 + (wid >> 2) * 4;
    const int nt0 = blockIdx.x * 16 + (wid & 3) * 4;

    float acc[4][4][4];
#pragma unroll
    for (int mi = 0; mi < 4; mi++)
#pragma unroll
        for (int ni = 0; ni < 4; ni++)
#pragma unroll
            for (int q = 0; q < 4; q++) acc[mi][ni][q] = 0.0f;

    uint4 ah[2][4], al[2][4];
    uint2 bh[2][4], bl[2][4];

#pragma unroll
    for (int mi = 0; mi < 4; mi++) {
        size_t o = (((size_t)(mt0 + mi) * KSTEPS + 0) * 32 + lane) * 4;
        ah[0][mi] = *(const uint4*)(g_ah + o);
        al[0][mi] = *(const uint4*)(g_al + o);
    }
#pragma unroll
    for (int ni = 0; ni < 4; ni++) {
        size_t o = (((size_t)(nt0 + ni) * KSTEPS + 0) * 32 + lane) * 2;
        bh[0][ni] = *(const uint2*)(g_bh + o);
        bl[0][ni] = *(const uint2*)(g_bl + o);
    }

#pragma unroll
    for (int ks = 0; ks < KSTEPS; ks++) {
        const int cur = ks & 1, nxt = cur ^ 1;
        if (ks + 1 < KSTEPS) {
#pragma unroll
            for (int mi = 0; mi < 4; mi++) {
                size_t o = (((size_t)(mt0 + mi) * KSTEPS + ks + 1) * 32 + lane) * 4;
                ah[nxt][mi] = *(const uint4*)(g_ah + o);
                al[nxt][mi] = *(const uint4*)(g_al + o);
            }
#pragma unroll
            for (int ni = 0; ni < 4; ni++) {
                size_t o = (((size_t)(nt0 + ni) * KSTEPS + ks + 1) * 32 + lane) * 2;
                bh[nxt][ni] = *(const uint2*)(g_bh + o);
                bl[nxt][ni] = *(const uint2*)(g_bl + o);
            }
        }
#pragma unroll
        for (int mi = 0; mi < 4; mi++)
#pragma unroll
            for (int ni = 0; ni < 4; ni++) {
                mma_bf16(acc[mi][ni], ah[cur][mi], bh[cur][ni]);
                mma_bf16(acc[mi][ni], al[cur][mi], bh[cur][ni]);
                mma_bf16(acc[mi][ni], ah[cur][mi], bl[cur][ni]);
            }
    }

#pragma unroll
    for (int ni = 0; ni < 4; ni++) {
        const int c = (nt0 + ni) * 8 + (lane & 3) * 2;
        const float bv0 = bih[c] + bhh[c];
        const float bv1 = bih[c + 1] + bhh[c + 1];
#pragma unroll
        for (int mi = 0; mi < 4; mi++) {
            const int m = (mt0 + mi) * 16 + (lane >> 2);
            float2 v0 = make_float2(acc[mi][ni][0] + bv0, acc[mi][ni][1] + bv1);
            float2 v1 = make_float2(acc[mi][ni][2] + bv0, acc[mi][ni][3] + bv1);
            *(float2*)(g_gx + (size_t)m * GATES + c) = v0;
            *(float2*)(g_gx + (size_t)(m + 8) * GATES + c) = v1;
        }
    }
}

// =====================================================================
// Kernel 2: LSTM recurrence. R6 change: weights 96 floats in regs (KRQ=24),
// only 32 in smem (KSQ=8) -> weight-LDS LSU cycles halve per step.
// =====================================================================
#define KRQ 24   // register float4-groups per row (96 floats)
#define KSQ 8    // smem float4-groups per row (32 floats)
#define WSP_BYTES (KSQ * 512 * 16)          // 64 KB
#define LSTM_SMEM (WSP_BYTES + 1024 + 4096)

__global__ __launch_bounds__(512, 1)
void lstm_kernel(const float* __restrict__ Whh) {
    extern __shared__ char smem[];
    ulonglong2* wsp2 = (ulonglong2*)smem;
    float* h0f = (float*)(smem + WSP_BYTES);
    float* h1f = h0f + 128;
    float2* ga = (float2*)(smem + WSP_BYTES + 1024);

    const int n = threadIdx.x;
    const int b0 = blockIdx.x * 2;
    const int b1 = b0 + 1;

    const float4* wrow4 = (const float4*)(Whh + (size_t)n * HID);
    ull wregp[2 * KRQ];
#pragma unroll
    for (int q = 0; q < KRQ; q++) {
        float4 v = wrow4[q];
        wregp[2 * q]     = pack2(v.x, v.y);
        wregp[2 * q + 1] = pack2(v.z, v.w);
    }
#pragma unroll
    for (int p = 0; p < KSQ; p++) {
        float4 v = wrow4[KRQ + p];
        ulonglong2 w;
        w.x = pack2(v.x, v.y);
        w.y = pack2(v.z, v.w);
        wsp2[p * 512 + n] = w;
    }

    if (n < 128) { h0f[n] = 0.0f; h1f[n] = 0.0f; }
    __syncthreads();

    const float* gx0p = g_gx + ((size_t)b0 * TSEQ) * GATES + n;
    const float* gx1p = g_gx + ((size_t)b1 * TSEQ) * GATES + n;
    float gxa = gx0p[0], gxb = gx1p[0];
    float c0 = 0.0f, c1 = 0.0f;

    for (int t = 0; t < TSEQ; t++) {
        float gna = 0.0f, gnb = 0.0f;
        if (t + 1 < TSEQ) {
            gna = gx0p[(size_t)(t + 1) * GATES];
            gnb = gx1p[(size_t)(t + 1) * GATES];
        }
        ull a0 = pack2(gxa, 0.0f);
        ull a1 = pack2(gxb, 0.0f);
        const ulonglong2* h02 = (const ulonglong2*)h0f;
        const ulonglong2* h12 = (const ulonglong2*)h1f;
#pragma unroll
        for (int q = 0; q < KRQ; q++) {
            ulonglong2 hA = h02[q];
            ulonglong2 hB = h12[q];
            a0 = ffma2(wregp[2 * q],     hA.x, a0);
            a0 = ffma2(wregp[2 * q + 1], hA.y, a0);
            a1 = ffma2(wregp[2 * q],     hB.x, a1);
            a1 = ffma2(wregp[2 * q + 1], hB.y, a1);
        }
#pragma unroll
        for (int p = 0; p < KSQ; p++) {
            ulonglong2 w  = wsp2[p * 512 + n];
            ulonglong2 hA = h02[KRQ + p];
            ulonglong2 hB = h12[KRQ + p];
            a0 = ffma2(w.x, hA.x, a0);
            a0 = ffma2(w.y, hA.y, a0);
            a1 = ffma2(w.x, hB.x, a1);
            a1 = ffma2(w.y, hB.y, a1);
        }
        float2 s0 = unpack2(a0), s1 = unpack2(a1);
        float pre0 = s0.x + s0.y, pre1 = s1.x + s1.y;
        float act0, act1;
        if (n >= 256 && n < 384) { act0 = tanh_f(pre0); act1 = tanh_f(pre1); }
        else                     { act0 = sig_f(pre0);  act1 = sig_f(pre1);  }
        ga[n] = make_float2(act0, act1);
        __syncthreads();
        if (n < 128) {
            float2 gi = ga[n], gf = ga[n + 128], gg = ga[n + 256], go = ga[n + 384];
            c0 = gf.x * c0 + gi.x * gg.x;
            c1 = gf.y * c1 + gi.y * gg.y;
            h0f[n] = go.x * tanh_f(c0);
            h1f[n] = go.y * tanh_f(c1);
        }
        __syncthreads();
        gxa = gna; gxb = gnb;
    }

    if (n < 128) {
        g_hfin[b0 * HID + n] = h0f[n];
        g_hfin[b1 * HID + n] = h1f[n];
    }
}

// =====================================================================
// Kernel 3: MLP head (unchanged)
// =====================================================================
__global__ __launch_bounds__(128)
void mlp_kernel(const float* __restrict__ W1, const float* __restrict__ b1,
                const float* __restrict__ W2, const float* __restrict__ b2,
                const float* __restrict__ W3, const float* __restrict__ b3,
                float* __restrict__ out) {
    __shared__ float h[128];
    __shared__ float h1[64];
    __shared__ float h2[32];
    const int b = blockIdx.x;
    const int t = threadIdx.x;

    h[t] = g_hfin[b * HID + t];
    __syncthreads();
    if (t < 64) {
        float s = b1[t];
        const float* w = W1 + t * 128;
#pragma unroll 8
        for (int k = 0; k < 128; k++) s += w[k] * h[k];
        h1[t] = fmaxf(s, 0.0f);
    }
    __syncthreads();
    if (t < 32) {
        float s = b2[t];
        const float* w = W2 + t * 64;
#pragma unroll 8
        for (int k = 0; k < 64; k++) s += w[k] * h1[k];
        h2[t] = fmaxf(s, 0.0f);
    }
    __syncthreads();
    if (t < 4) {
        float s = b3[t];
        const float* w = W3 + t * 32;
#pragma unroll
        for (int k = 0; k < 32; k++) s += w[k] * h2[k];
        out[b * 4 + t] = s;
    }
}

// =====================================================================
extern "C" void kernel_launch(void* const* d_in, const int* in_sizes, int n_in,
                              void* d_out, int out_size) {
    const float* x    = (const float*)d_in[0];
    const float* Wih  = (const float*)d_in[1];
    const float* Whh  = (const float*)d_in[2];
    const float* bih  = (const float*)d_in[3];
    const float* bhh  = (const float*)d_in[4];
    const float* W1   = (const float*)d_in[5];
    const float* b1   = (const float*)d_in[6];
    const float* W2   = (const float*)d_in[7];
    const float* b2   = (const float*)d_in[8];
    const float* W3   = (const float*)d_in[9];
    const float* b3   = (const float*)d_in[10];
    float* out = (float*)d_out;

    cudaFuncSetAttribute(lstm_kernel, cudaFuncAttributeMaxDynamicSharedMemorySize, LSTM_SMEM);

    int total_warps = MTILES * KSTEPS + NTILES * KSTEPS;
    prep_frags<<<(total_warps + 7) / 8, 256>>>(x, Wih);

    dim3 ggrid(GATES / 128, (BATCH * TSEQ) / 128);   // (4, 1024)
    gemm_mma<<<ggrid, 256>>>(bih, bhh);

    lstm_kernel<<<BATCH / 2, 512, LSTM_SMEM>>>(Whh);
    mlp_kernel<<<BATCH, 128>>>(W1, b1, W2, b2, W3, b3, out);
}

// round 8
// speedup vs baseline: 1.5088x; 1.3128x over previous
#include <cuda_runtime.h>
#include <cuda_bf16.h>
#include <cstdint>
#include <cstddef>

#define TSEQ  512
#define HID   128
#define GATES 512
#define INP   256
#define BATCH 256

typedef unsigned long long ull;

// -------- device-global scratch (no runtime allocation allowed) --------
__device__ float g_gx[(size_t)BATCH * TSEQ * GATES];   // 256 MB
__device__ float g_hfin[BATCH * HID];

#define MTILES 8192                 // (BATCH*TSEQ)/16
#define NTILES 64                   // GATES/8
#define KSTEPS 16                   // INP/16
__device__ uint32_t g_ah[(size_t)MTILES * KSTEPS * 32 * 4];  // 64 MB
__device__ uint32_t g_al[(size_t)MTILES * KSTEPS * 32 * 4];  // 64 MB
__device__ uint32_t g_bh[(size_t)NTILES * KSTEPS * 32 * 2];  // 256 KB
__device__ uint32_t g_bl[(size_t)NTILES * KSTEPS * 32 * 2];  // 256 KB

// ---------------- helpers ----------------
__device__ __forceinline__ ull ffma2(ull a, ull b, ull c) {
    ull d; asm("fma.rn.f32x2 %0, %1, %2, %3;" : "=l"(d) : "l"(a), "l"(b), "l"(c));
    return d;
}
__device__ __forceinline__ ull pack2(float x, float y) {
    ull r; asm("mov.b64 %0, {%1, %2};" : "=l"(r) : "f"(x), "f"(y)); return r;
}
__device__ __forceinline__ float2 unpack2(ull v) {
    float2 r; asm("mov.b64 {%0, %1}, %2;" : "=f"(r.x), "=f"(r.y) : "l"(v)); return r;
}
__device__ __forceinline__ float sig_f(float x) {
    return __fdividef(1.0f, 1.0f + __expf(-x));
}
__device__ __forceinline__ float tanh_f(float x) {
    return __fdividef(2.0f, 1.0f + __expf(-2.0f * x)) - 1.0f;
}
// pack two fp32 -> bf16x2 (lo element in low 16 bits)
__device__ __forceinline__ uint32_t bfpair(float lo, float hi) {
    uint32_t r; asm("cvt.rn.bf16x2.f32 %0, %1, %2;" : "=r"(r) : "f"(hi), "f"(lo));
    return r;
}
// hi/lo split of a pair: h = bf16 pair, l = residual pair
__device__ __forceinline__ void split_pair(float e0, float e1, uint32_t& h, uint32_t& l) {
    h = bfpair(e0, e1);
    float h0 = __uint_as_float(h << 16);
    float h1 = __uint_as_float(h & 0xFFFF0000u);
    l = bfpair(e0 - h0, e1 - h1);
}

__device__ __forceinline__ void mma_bf16(float* c, const uint4& a, const uint2& b) {
    asm volatile(
        "mma.sync.aligned.m16n8k16.row.col.f32.bf16.bf16.f32 "
        "{%0,%1,%2,%3}, {%4,%5,%6,%7}, {%8,%9}, {%0,%1,%2,%3};"
        : "+f"(c[0]), "+f"(c[1]), "+f"(c[2]), "+f"(c[3])
        : "r"(a.x), "r"(a.y), "r"(a.z), "r"(a.w), "r"(b.x), "r"(b.y));
}

// =====================================================================
// Kernel 0: convert x and W_ih into fragment-ordered bf16 hi/lo arrays.
// =====================================================================
__global__ __launch_bounds__(256)
void prep_frags(const float* __restrict__ x, const float* __restrict__ Wih) {
    int gw = (blockIdx.x * 256 + threadIdx.x) >> 5;
    int lane = threadIdx.x & 31;
    if (gw < MTILES * KSTEPS) {
        int tile = gw >> 4, ks = gw & 15;
        int m = tile * 16 + (lane >> 2);
        int k = ks * 16 + (lane & 3) * 2;
        const float* base = x + (size_t)m * INP + k;
        float2 p0 = *(const float2*)(base);
        float2 p1 = *(const float2*)(base + 8 * INP);
        float2 p2 = *(const float2*)(base + 8);
        float2 p3 = *(const float2*)(base + 8 * INP + 8);
        uint4 h, l;
        split_pair(p0.x, p0.y, h.x, l.x);
        split_pair(p1.x, p1.y, h.y, l.y);
        split_pair(p2.x, p2.y, h.z, l.z);
        split_pair(p3.x, p3.y, h.w, l.w);
        size_t o = ((size_t)gw * 32 + lane) * 4;
        *(uint4*)(g_ah + o) = h;
        *(uint4*)(g_al + o) = l;
    } else if (gw < MTILES * KSTEPS + NTILES * KSTEPS) {
        int w = gw - MTILES * KSTEPS;
        int tile = w >> 4, ks = w & 15;
        int n = tile * 8 + (lane >> 2);
        int k = ks * 16 + (lane & 3) * 2;
        const float* base = Wih + (size_t)n * INP + k;
        float2 p0 = *(const float2*)(base);
        float2 p1 = *(const float2*)(base + 8);
        uint2 h, l;
        split_pair(p0.x, p0.y, h.x, l.x);
        split_pair(p1.x, p1.y, h.y, l.y);
        size_t o = ((size_t)w * 32 + lane) * 2;
        *(uint2*)(g_bh + o) = h;
        *(uint2*)(g_bl + o) = l;
    }
}

// =====================================================================
// Kernel 1: gx = x@W_ih^T + bias via mma.sync bf16 hi/lo (3 passes).
// R7: warp tile 32x32, CTA 64x128, ~111 regs -> 2 CTAs/SM (4 warps/SMSP)
// to hide fragment-LDG latency behind HMMA.
// =====================================================================
__global__ __launch_bounds__(256, 2)
void gemm_mma(const float* __restrict__ bih, const float* __restrict__ bhh) {
    const int wid = threadIdx.x >> 5;
    const int lane = threadIdx.x & 31;
    const int mt0 = blockIdx.y * 4 + (wid >> 2) * 2;   // 2 m16-tiles per warp
    const int nt0 = blockIdx.x * 16 + (wid & 3) * 4;   // 4 n8-tiles per warp

    float acc[2][4][4];
#pragma unroll
    for (int mi = 0; mi < 2; mi++)
#pragma unroll
        for (int ni = 0; ni < 4; ni++)
#pragma unroll
            for (int q = 0; q < 4; q++) acc[mi][ni][q] = 0.0f;

    uint4 ah[2][2], al[2][2];
    uint2 bh[2][4], bl[2][4];

#pragma unroll
    for (int mi = 0; mi < 2; mi++) {
        size_t o = (((size_t)(mt0 + mi) * KSTEPS + 0) * 32 + lane) * 4;
        ah[0][mi] = *(const uint4*)(g_ah + o);
        al[0][mi] = *(const uint4*)(g_al + o);
    }
#pragma unroll
    for (int ni = 0; ni < 4; ni++) {
        size_t o = (((size_t)(nt0 + ni) * KSTEPS + 0) * 32 + lane) * 2;
        bh[0][ni] = *(const uint2*)(g_bh + o);
        bl[0][ni] = *(const uint2*)(g_bl + o);
    }

#pragma unroll
    for (int ks = 0; ks < KSTEPS; ks++) {
        const int cur = ks & 1, nxt = cur ^ 1;
        if (ks + 1 < KSTEPS) {
#pragma unroll
            for (int mi = 0; mi < 2; mi++) {
                size_t o = (((size_t)(mt0 + mi) * KSTEPS + ks + 1) * 32 + lane) * 4;
                ah[nxt][mi] = *(const uint4*)(g_ah + o);
                al[nxt][mi] = *(const uint4*)(g_al + o);
            }
#pragma unroll
            for (int ni = 0; ni < 4; ni++) {
                size_t o = (((size_t)(nt0 + ni) * KSTEPS + ks + 1) * 32 + lane) * 2;
                bh[nxt][ni] = *(const uint2*)(g_bh + o);
                bl[nxt][ni] = *(const uint2*)(g_bl + o);
            }
        }
#pragma unroll
        for (int mi = 0; mi < 2; mi++)
#pragma unroll
            for (int ni = 0; ni < 4; ni++) {
                mma_bf16(acc[mi][ni], ah[cur][mi], bh[cur][ni]);
                mma_bf16(acc[mi][ni], al[cur][mi], bh[cur][ni]);
                mma_bf16(acc[mi][ni], ah[cur][mi], bl[cur][ni]);
            }
    }

#pragma unroll
    for (int ni = 0; ni < 4; ni++) {
        const int c = (nt0 + ni) * 8 + (lane & 3) * 2;
        const float bv0 = bih[c] + bhh[c];
        const float bv1 = bih[c + 1] + bhh[c + 1];
#pragma unroll
        for (int mi = 0; mi < 2; mi++) {
            const int m = (mt0 + mi) * 16 + (lane >> 2);
            float2 v0 = make_float2(acc[mi][ni][0] + bv0, acc[mi][ni][1] + bv1);
            float2 v1 = make_float2(acc[mi][ni][2] + bv0, acc[mi][ni][3] + bv1);
            *(float2*)(g_gx + (size_t)m * GATES + c) = v0;
            *(float2*)(g_gx + (size_t)(m + 8) * GATES + c) = v1;
        }
    }
}

// =====================================================================
// Kernel 2: LSTM recurrence (unchanged from R6: KRQ=24/KSQ=8)
// =====================================================================
#define KRQ 24   // register float4-groups per row (96 floats)
#define KSQ 8    // smem float4-groups per row (32 floats)
#define WSP_BYTES (KSQ * 512 * 16)          // 64 KB
#define LSTM_SMEM (WSP_BYTES + 1024 + 4096)

__global__ __launch_bounds__(512, 1)
void lstm_kernel(const float* __restrict__ Whh) {
    extern __shared__ char smem[];
    ulonglong2* wsp2 = (ulonglong2*)smem;
    float* h0f = (float*)(smem + WSP_BYTES);
    float* h1f = h0f + 128;
    float2* ga = (float2*)(smem + WSP_BYTES + 1024);

    const int n = threadIdx.x;
    const int b0 = blockIdx.x * 2;
    const int b1 = b0 + 1;

    const float4* wrow4 = (const float4*)(Whh + (size_t)n * HID);
    ull wregp[2 * KRQ];
#pragma unroll
    for (int q = 0; q < KRQ; q++) {
        float4 v = wrow4[q];
        wregp[2 * q]     = pack2(v.x, v.y);
        wregp[2 * q + 1] = pack2(v.z, v.w);
    }
#pragma unroll
    for (int p = 0; p < KSQ; p++) {
        float4 v = wrow4[KRQ + p];
        ulonglong2 w;
        w.x = pack2(v.x, v.y);
        w.y = pack2(v.z, v.w);
        wsp2[p * 512 + n] = w;
    }

    if (n < 128) { h0f[n] = 0.0f; h1f[n] = 0.0f; }
    __syncthreads();

    const float* gx0p = g_gx + ((size_t)b0 * TSEQ) * GATES + n;
    const float* gx1p = g_gx + ((size_t)b1 * TSEQ) * GATES + n;
    float gxa = gx0p[0], gxb = gx1p[0];
    float c0 = 0.0f, c1 = 0.0f;

    for (int t = 0; t < TSEQ; t++) {
        float gna = 0.0f, gnb = 0.0f;
        if (t + 1 < TSEQ) {
            gna = gx0p[(size_t)(t + 1) * GATES];
            gnb = gx1p[(size_t)(t + 1) * GATES];
        }
        ull a0 = pack2(gxa, 0.0f);
        ull a1 = pack2(gxb, 0.0f);
        const ulonglong2* h02 = (const ulonglong2*)h0f;
        const ulonglong2* h12 = (const ulonglong2*)h1f;
#pragma unroll
        for (int q = 0; q < KRQ; q++) {
            ulonglong2 hA = h02[q];
            ulonglong2 hB = h12[q];
            a0 = ffma2(wregp[2 * q],     hA.x, a0);
            a0 = ffma2(wregp[2 * q + 1], hA.y, a0);
            a1 = ffma2(wregp[2 * q],     hB.x, a1);
            a1 = ffma2(wregp[2 * q + 1], hB.y, a1);
        }
#pragma unroll
        for (int p = 0; p < KSQ; p++) {
            ulonglong2 w  = wsp2[p * 512 + n];
            ulonglong2 hA = h02[KRQ + p];
            ulonglong2 hB = h12[KRQ + p];
            a0 = ffma2(w.x, hA.x, a0);
            a0 = ffma2(w.y, hA.y, a0);
            a1 = ffma2(w.x, hB.x, a1);
            a1 = ffma2(w.y, hB.y, a1);
        }
        float2 s0 = unpack2(a0), s1 = unpack2(a1);
        float pre0 = s0.x + s0.y, pre1 = s1.x + s1.y;
        float act0, act1;
        if (n >= 256 && n < 384) { act0 = tanh_f(pre0); act1 = tanh_f(pre1); }
        else                     { act0 = sig_f(pre0);  act1 = sig_f(pre1);  }
        ga[n] = make_float2(act0, act1);
        __syncthreads();
        if (n < 128) {
            float2 gi = ga[n], gf = ga[n + 128], gg = ga[n + 256], go = ga[n + 384];
            c0 = gf.x * c0 + gi.x * gg.x;
            c1 = gf.y * c1 + gi.y * gg.y;
            h0f[n] = go.x * tanh_f(c0);
            h1f[n] = go.y * tanh_f(c1);
        }
        __syncthreads();
        gxa = gna; gxb = gnb;
    }

    if (n < 128) {
        g_hfin[b0 * HID + n] = h0f[n];
        g_hfin[b1 * HID + n] = h1f[n];
    }
}

// =====================================================================
// Kernel 3: MLP head (unchanged)
// =====================================================================
__global__ __launch_bounds__(128)
void mlp_kernel(const float* __restrict__ W1, const float* __restrict__ b1,
                const float* __restrict__ W2, const float* __restrict__ b2,
                const float* __restrict__ W3, const float* __restrict__ b3,
                float* __restrict__ out) {
    __shared__ float h[128];
    __shared__ float h1[64];
    __shared__ float h2[32];
    const int b = blockIdx.x;
    const int t = threadIdx.x;

    h[t] = g_hfin[b * HID + t];
    __syncthreads();
    if (t < 64) {
        float s = b1[t];
        const float* w = W1 + t * 128;
#pragma unroll 8
        for (int k = 0; k < 128; k++) s += w[k] * h[k];
        h1[t] = fmaxf(s, 0.0f);
    }
    __syncthreads();
    if (t < 32) {
        float s = b2[t];
        const float* w = W2 + t * 64;
#pragma unroll 8
        for (int k = 0; k < 64; k++) s += w[k] * h1[k];
        h2[t] = fmaxf(s, 0.0f);
    }
    __syncthreads();
    if (t < 4) {
        float s = b3[t];
        const float* w = W3 + t * 32;
#pragma unroll
        for (int k = 0; k < 32; k++) s += w[k] * h2[k];
        out[b * 4 + t] = s;
    }
}

// =====================================================================
extern "C" void kernel_launch(void* const* d_in, const int* in_sizes, int n_in,
                              void* d_out, int out_size) {
    const float* x    = (const float*)d_in[0];
    const float* Wih  = (const float*)d_in[1];
    const float* Whh  = (const float*)d_in[2];
    const float* bih  = (const float*)d_in[3];
    const float* bhh  = (const float*)d_in[4];
    const float* W1   = (const float*)d_in[5];
    const float* b1   = (const float*)d_in[6];
    const float* W2   = (const float*)d_in[7];
    const float* b2   = (const float*)d_in[8];
    const float* W3   = (const float*)d_in[9];
    const float* b3   = (const float*)d_in[10];
    float* out = (float*)d_out;

    cudaFuncSetAttribute(lstm_kernel, cudaFuncAttributeMaxDynamicSharedMemorySize, LSTM_SMEM);

    int total_warps = MTILES * KSTEPS + NTILES * KSTEPS;
    prep_frags<<<(total_warps + 7) / 8, 256>>>(x, Wih);

    // CTA tile 64(M) x 128(N): grid (N-tiles, M-tiles); N adjacent for L2 A-reuse
    dim3 ggrid(GATES / 128, (BATCH * TSEQ) / 64);   // (4, 2048)
    gemm_mma<<<ggrid, 256>>>(bih, bhh);

    lstm_kernel<<<BATCH / 2, 512, LSTM_SMEM>>>(Whh);
    mlp_kernel<<<BATCH, 128>>>(W1, b1, W2, b2, W3, b3, out);
}

// round 9
// speedup vs baseline: 1.8751x; 1.2428x over previous
#include <cuda_runtime.h>
#include <cuda_bf16.h>
#include <cstdint>
#include <cstddef>

#define TSEQ  512
#define HID   128
#define GATES 512
#define INP   256
#define BATCH 256

typedef unsigned long long ull;

// -------- device-global scratch (no runtime allocation allowed) --------
__device__ float g_gx[(size_t)BATCH * TSEQ * GATES];   // 256 MB
__device__ float g_hfin[BATCH * HID];

#define MTILES 8192                 // (BATCH*TSEQ)/16
#define NTILES 64                   // GATES/8
#define KSTEPS 16                   // INP/16
__device__ uint32_t g_ah[(size_t)MTILES * KSTEPS * 32 * 4];  // 64 MB
__device__ uint32_t g_al[(size_t)MTILES * KSTEPS * 32 * 4];  // 64 MB
__device__ uint32_t g_bh[(size_t)NTILES * KSTEPS * 32 * 2];  // 256 KB
__device__ uint32_t g_bl[(size_t)NTILES * KSTEPS * 32 * 2];  // 256 KB

// ---------------- helpers ----------------
__device__ __forceinline__ ull ffma2(ull a, ull b, ull c) {
    ull d; asm("fma.rn.f32x2 %0, %1, %2, %3;" : "=l"(d) : "l"(a), "l"(b), "l"(c));
    return d;
}
__device__ __forceinline__ ull pack2(float x, float y) {
    ull r; asm("mov.b64 %0, {%1, %2};" : "=l"(r) : "f"(x), "f"(y)); return r;
}
__device__ __forceinline__ float2 unpack2(ull v) {
    float2 r; asm("mov.b64 {%0, %1}, %2;" : "=f"(r.x), "=f"(r.y) : "l"(v)); return r;
}
__device__ __forceinline__ float sig_f(float x) {
    return __fdividef(1.0f, 1.0f + __expf(-x));
}
__device__ __forceinline__ float tanh_f(float x) {
    return __fdividef(2.0f, 1.0f + __expf(-2.0f * x)) - 1.0f;
}
// pack two fp32 -> bf16x2 (lo element in low 16 bits)
__device__ __forceinline__ uint32_t bfpair(float lo, float hi) {
    uint32_t r; asm("cvt.rn.bf16x2.f32 %0, %1, %2;" : "=r"(r) : "f"(hi), "f"(lo));
    return r;
}
// hi/lo split of a pair: h = bf16 pair, l = residual pair
__device__ __forceinline__ void split_pair(float e0, float e1, uint32_t& h, uint32_t& l) {
    h = bfpair(e0, e1);
    float h0 = __uint_as_float(h << 16);
    float h1 = __uint_as_float(h & 0xFFFF0000u);
    l = bfpair(e0 - h0, e1 - h1);
}

__device__ __forceinline__ void mma_bf16(float* c, const uint4& a, const uint2& b) {
    asm volatile(
        "mma.sync.aligned.m16n8k16.row.col.f32.bf16.bf16.f32 "
        "{%0,%1,%2,%3}, {%4,%5,%6,%7}, {%8,%9}, {%0,%1,%2,%3};"
        : "+f"(c[0]), "+f"(c[1]), "+f"(c[2]), "+f"(c[3])
        : "r"(a.x), "r"(a.y), "r"(a.z), "r"(a.w), "r"(b.x), "r"(b.y));
}

// =====================================================================
// Kernel 0: convert x and W_ih into fragment-ordered bf16 hi/lo arrays.
// =====================================================================
__global__ __launch_bounds__(256)
void prep_frags(const float* __restrict__ x, const float* __restrict__ Wih) {
    int gw = (blockIdx.x * 256 + threadIdx.x) >> 5;
    int lane = threadIdx.x & 31;
    if (gw < MTILES * KSTEPS) {
        int tile = gw >> 4, ks = gw & 15;
        int m = tile * 16 + (lane >> 2);
        int k = ks * 16 + (lane & 3) * 2;
        const float* base = x + (size_t)m * INP + k;
        float2 p0 = *(const float2*)(base);
        float2 p1 = *(const float2*)(base + 8 * INP);
        float2 p2 = *(const float2*)(base + 8);
        float2 p3 = *(const float2*)(base + 8 * INP + 8);
        uint4 h, l;
        split_pair(p0.x, p0.y, h.x, l.x);
        split_pair(p1.x, p1.y, h.y, l.y);
        split_pair(p2.x, p2.y, h.z, l.z);
        split_pair(p3.x, p3.y, h.w, l.w);
        size_t o = ((size_t)gw * 32 + lane) * 4;
        *(uint4*)(g_ah + o) = h;
        *(uint4*)(g_al + o) = l;
    } else if (gw < MTILES * KSTEPS + NTILES * KSTEPS) {
        int w = gw - MTILES * KSTEPS;
        int tile = w >> 4, ks = w & 15;
        int n = tile * 8 + (lane >> 2);
        int k = ks * 16 + (lane & 3) * 2;
        const float* base = Wih + (size_t)n * INP + k;
        float2 p0 = *(const float2*)(base);
        float2 p1 = *(const float2*)(base + 8);
        uint2 h, l;
        split_pair(p0.x, p0.y, h.x, l.x);
        split_pair(p1.x, p1.y, h.y, l.y);
        size_t o = ((size_t)w * 32 + lane) * 2;
        *(uint2*)(g_bh + o) = h;
        *(uint2*)(g_bl + o) = l;
    }
}

// =====================================================================
// Kernel 1: gx = x@W_ih^T + bias via mma.sync bf16 hi/lo (3 passes).
// (unchanged from R7: warp tile 32x32, 2 CTAs/SM)
// =====================================================================
__global__ __launch_bounds__(256, 2)
void gemm_mma(const float* __restrict__ bih, const float* __restrict__ bhh) {
    const int wid = threadIdx.x >> 5;
    const int lane = threadIdx.x & 31;
    const int mt0 = blockIdx.y * 4 + (wid >> 2) * 2;
    const int nt0 = blockIdx.x * 16 + (wid & 3) * 4;

    float acc[2][4][4];
#pragma unroll
    for (int mi = 0; mi < 2; mi++)
#pragma unroll
        for (int ni = 0; ni < 4; ni++)
#pragma unroll
            for (int q = 0; q < 4; q++) acc[mi][ni][q] = 0.0f;

    uint4 ah[2][2], al[2][2];
    uint2 bh[2][4], bl[2][4];

#pragma unroll
    for (int mi = 0; mi < 2; mi++) {
        size_t o = (((size_t)(mt0 + mi) * KSTEPS + 0) * 32 + lane) * 4;
        ah[0][mi] = *(const uint4*)(g_ah + o);
        al[0][mi] = *(const uint4*)(g_al + o);
    }
#pragma unroll
    for (int ni = 0; ni < 4; ni++) {
        size_t o = (((size_t)(nt0 + ni) * KSTEPS + 0) * 32 + lane) * 2;
        bh[0][ni] = *(const uint2*)(g_bh + o);
        bl[0][ni] = *(const uint2*)(g_bl + o);
    }

#pragma unroll
    for (int ks = 0; ks < KSTEPS; ks++) {
        const int cur = ks & 1, nxt = cur ^ 1;
        if (ks + 1 < KSTEPS) {
#pragma unroll
            for (int mi = 0; mi < 2; mi++) {
                size_t o = (((size_t)(mt0 + mi) * KSTEPS + ks + 1) * 32 + lane) * 4;
                ah[nxt][mi] = *(const uint4*)(g_ah + o);
                al[nxt][mi] = *(const uint4*)(g_al + o);
            }
#pragma unroll
            for (int ni = 0; ni < 4; ni++) {
                size_t o = (((size_t)(nt0 + ni) * KSTEPS + ks + 1) * 32 + lane) * 2;
                bh[nxt][ni] = *(const uint2*)(g_bh + o);
                bl[nxt][ni] = *(const uint2*)(g_bl + o);
            }
        }
#pragma unroll
        for (int mi = 0; mi < 2; mi++)
#pragma unroll
            for (int ni = 0; ni < 4; ni++) {
                mma_bf16(acc[mi][ni], ah[cur][mi], bh[cur][ni]);
                mma_bf16(acc[mi][ni], al[cur][mi], bh[cur][ni]);
                mma_bf16(acc[mi][ni], ah[cur][mi], bl[cur][ni]);
            }
    }

#pragma unroll
    for (int ni = 0; ni < 4; ni++) {
        const int c = (nt0 + ni) * 8 + (lane & 3) * 2;
        const float bv0 = bih[c] + bhh[c];
        const float bv1 = bih[c + 1] + bhh[c + 1];
#pragma unroll
        for (int mi = 0; mi < 2; mi++) {
            const int m = (mt0 + mi) * 16 + (lane >> 2);
            float2 v0 = make_float2(acc[mi][ni][0] + bv0, acc[mi][ni][1] + bv1);
            float2 v1 = make_float2(acc[mi][ni][2] + bv0, acc[mi][ni][3] + bv1);
            *(float2*)(g_gx + (size_t)m * GATES + c) = v0;
            *(float2*)(g_gx + (size_t)(m + 8) * GATES + c) = v1;
        }
    }
}

// =====================================================================
// Kernel 2: LSTM recurrence. R8: 256 threads, 2 gates/thread (n, n+256)
// -> each h-broadcast LDS feeds 2 gates x 2 batches; h-LDS traffic halves.
// Weights: KRQ=22 f4-groups/row in regs (88 floats x 2 rows = 176 regs),
// KSQ=10 in smem.
// =====================================================================
#define KRQ 22
#define KSQ 10
#define WSP_BYTES (KSQ * 512 * 16)          // 80 KB
#define LSTM_SMEM (WSP_BYTES + 1024 + 4096)

__global__ __launch_bounds__(256, 1)
void lstm_kernel(const float* __restrict__ Whh) {
    extern __shared__ char smem[];
    ulonglong2* wsp2 = (ulonglong2*)smem;                  // [KSQ][512]
    float* h0f = (float*)(smem + WSP_BYTES);               // 128 floats
    float* h1f = h0f + 128;
    float2* ga = (float2*)(smem + WSP_BYTES + 1024);       // [512]

    const int t0 = threadIdx.x;       // gate n0 = t0, gate n1 = t0 + 256
    const int n1 = t0 + 256;
    const int b0 = blockIdx.x * 2;
    const int b1 = b0 + 1;

    // preload weights for both rows
    const float4* w0row = (const float4*)(Whh + (size_t)t0 * HID);
    const float4* w1row = (const float4*)(Whh + (size_t)n1 * HID);
    ull wr0[2 * KRQ], wr1[2 * KRQ];
#pragma unroll
    for (int q = 0; q < KRQ; q++) {
        float4 v0 = w0row[q];
        wr0[2 * q]     = pack2(v0.x, v0.y);
        wr0[2 * q + 1] = pack2(v0.z, v0.w);
        float4 v1 = w1row[q];
        wr1[2 * q]     = pack2(v1.x, v1.y);
        wr1[2 * q + 1] = pack2(v1.z, v1.w);
    }
#pragma unroll
    for (int p = 0; p < KSQ; p++) {
        float4 v0 = w0row[KRQ + p];
        ulonglong2 w;
        w.x = pack2(v0.x, v0.y);
        w.y = pack2(v0.z, v0.w);
        wsp2[p * 512 + t0] = w;
        float4 v1 = w1row[KRQ + p];
        w.x = pack2(v1.x, v1.y);
        w.y = pack2(v1.z, v1.w);
        wsp2[p * 512 + n1] = w;
    }

    if (t0 < 128) { h0f[t0] = 0.0f; h1f[t0] = 0.0f; }
    __syncthreads();

    const float* gxb0 = g_gx + ((size_t)b0 * TSEQ) * GATES;
    const float* gxb1 = g_gx + ((size_t)b1 * TSEQ) * GATES;
    // gx values for (gate, batch): [n0b0, n0b1, n1b0, n1b1]
    float gx00 = gxb0[t0], gx01 = gxb1[t0];
    float gx10 = gxb0[n1], gx11 = gxb1[n1];
    float c0 = 0.0f, c1 = 0.0f;

    for (int t = 0; t < TSEQ; t++) {
        float p00 = 0.f, p01 = 0.f, p10 = 0.f, p11 = 0.f;
        if (t + 1 < TSEQ) {
            size_t o = (size_t)(t + 1) * GATES;
            p00 = gxb0[o + t0]; p01 = gxb1[o + t0];
            p10 = gxb0[o + n1]; p11 = gxb1[o + n1];
        }
        ull a00 = pack2(gx00, 0.0f);
        ull a01 = pack2(gx01, 0.0f);
        ull a10 = pack2(gx10, 0.0f);
        ull a11 = pack2(gx11, 0.0f);
        const ulonglong2* h02 = (const ulonglong2*)h0f;   // 32 groups
        const ulonglong2* h12 = (const ulonglong2*)h1f;
#pragma unroll
        for (int q = 0; q < KRQ; q++) {
            ulonglong2 hA = h02[q];
            ulonglong2 hB = h12[q];
            a00 = ffma2(wr0[2 * q],     hA.x, a00);
            a00 = ffma2(wr0[2 * q + 1], hA.y, a00);
            a01 = ffma2(wr0[2 * q],     hB.x, a01);
            a01 = ffma2(wr0[2 * q + 1], hB.y, a01);
            a10 = ffma2(wr1[2 * q],     hA.x, a10);
            a10 = ffma2(wr1[2 * q + 1], hA.y, a10);
            a11 = ffma2(wr1[2 * q],     hB.x, a11);
            a11 = ffma2(wr1[2 * q + 1], hB.y, a11);
        }
#pragma unroll
        for (int p = 0; p < KSQ; p++) {
            ulonglong2 w0 = wsp2[p * 512 + t0];
            ulonglong2 w1 = wsp2[p * 512 + n1];
            ulonglong2 hA = h02[KRQ + p];
            ulonglong2 hB = h12[KRQ + p];
            a00 = ffma2(w0.x, hA.x, a00);
            a00 = ffma2(w0.y, hA.y, a00);
            a01 = ffma2(w0.x, hB.x, a01);
            a01 = ffma2(w0.y, hB.y, a01);
            a10 = ffma2(w1.x, hA.x, a10);
            a10 = ffma2(w1.y, hA.y, a10);
            a11 = ffma2(w1.x, hB.x, a11);
            a11 = ffma2(w1.y, hB.y, a11);
        }
        float2 s00 = unpack2(a00), s01 = unpack2(a01);
        float2 s10 = unpack2(a10), s11 = unpack2(a11);
        float pre00 = s00.x + s00.y, pre01 = s01.x + s01.y;   // gate n0 (i or f)
        float pre10 = s10.x + s10.y, pre11 = s11.x + s11.y;   // gate n1 (g or o)
        // n0 in [0,256): i/f -> sigmoid. n1 in [256,512): g (t0<128) tanh, else o sigmoid.
        float act00 = sig_f(pre00), act01 = sig_f(pre01);
        float act10, act11;
        if (t0 < 128) { act10 = tanh_f(pre10); act11 = tanh_f(pre11); }
        else          { act10 = sig_f(pre10);  act11 = sig_f(pre11);  }
        ga[t0] = make_float2(act00, act01);
        ga[n1] = make_float2(act10, act11);
        __syncthreads();
        if (t0 < 128) {
            float2 gi = ga[t0], gf = ga[t0 + 128], gg = ga[t0 + 256], go = ga[t0 + 384];
            c0 = gf.x * c0 + gi.x * gg.x;
            c1 = gf.y * c1 + gi.y * gg.y;
            h0f[t0] = go.x * tanh_f(c0);
            h1f[t0] = go.y * tanh_f(c1);
        }
        __syncthreads();
        gx00 = p00; gx01 = p01; gx10 = p10; gx11 = p11;
    }

    if (t0 < 128) {
        g_hfin[b0 * HID + t0] = h0f[t0];
        g_hfin[b1 * HID + t0] = h1f[t0];
    }
}

// =====================================================================
// Kernel 3: MLP head (unchanged)
// =====================================================================
__global__ __launch_bounds__(128)
void mlp_kernel(const float* __restrict__ W1, const float* __restrict__ b1,
                const float* __restrict__ W2, const float* __restrict__ b2,
                const float* __restrict__ W3, const float* __restrict__ b3,
                float* __restrict__ out) {
    __shared__ float h[128];
    __shared__ float h1[64];
    __shared__ float h2[32];
    const int b = blockIdx.x;
    const int t = threadIdx.x;

    h[t] = g_hfin[b * HID + t];
    __syncthreads();
    if (t < 64) {
        float s = b1[t];
        const float* w = W1 + t * 128;
#pragma unroll 8
        for (int k = 0; k < 128; k++) s += w[k] * h[k];
        h1[t] = fmaxf(s, 0.0f);
    }
    __syncthreads();
    if (t < 32) {
        float s = b2[t];
        const float* w = W2 + t * 64;
#pragma unroll 8
        for (int k = 0; k < 64; k++) s += w[k] * h1[k];
        h2[t] = fmaxf(s, 0.0f);
    }
    __syncthreads();
    if (t < 4) {
        float s = b3[t];
        const float* w = W3 + t * 32;
#pragma unroll
        for (int k = 0; k < 32; k++) s += w[k] * h2[k];
        out[b * 4 + t] = s;
    }
}

// =====================================================================
extern "C" void kernel_launch(void* const* d_in, const int* in_sizes, int n_in,
                              void* d_out, int out_size) {
    const float* x    = (const float*)d_in[0];
    const float* Wih  = (const float*)d_in[1];
    const float* Whh  = (const float*)d_in[2];
    const float* bih  = (const float*)d_in[3];
    const float* bhh  = (const float*)d_in[4];
    const float* W1   = (const float*)d_in[5];
    const float* b1   = (const float*)d_in[6];
    const float* W2   = (const float*)d_in[7];
    const float* b2   = (const float*)d_in[8];
    const float* W3   = (const float*)d_in[9];
    const float* b3   = (const float*)d_in[10];
    float* out = (float*)d_out;

    cudaFuncSetAttribute(lstm_kernel, cudaFuncAttributeMaxDynamicSharedMemorySize, LSTM_SMEM);

    int total_warps = MTILES * KSTEPS + NTILES * KSTEPS;
    prep_frags<<<(total_warps + 7) / 8, 256>>>(x, Wih);

    dim3 ggrid(GATES / 128, (BATCH * TSEQ) / 64);   // (4, 2048)
    gemm_mma<<<ggrid, 256>>>(bih, bhh);

    lstm_kernel<<<BATCH / 2, 256, LSTM_SMEM>>>(Whh);
    mlp_kernel<<<BATCH, 128>>>(W1, b1, W2, b2, W3, b3, out);
}